// round 13
// baseline (speedup 1.0000x reference)
#include <cuda_runtime.h>
#include <cuda_fp16.h>
#include <cstdint>
#include <cstddef>

#define TOKENS 32768
#define DIM    1024
#define HMID   512
#define HLOW   256

#if defined(__CUDA_ARCH_FEAT_SM103_ALL) || defined(__CUDA_ARCH_FEAT_SM100_ALL) || \
    (defined(__CUDA_ARCH_SPECIFIC__) && (__CUDA_ARCH_SPECIFIC__ >= 1000))
#define TCGEN_OK 1
#else
#define TCGEN_OK 0
#endif

// ---------------- static device scratch (fp16x2 packed in u32) ----------------
__device__ uint32_t g_h0[(size_t)TOKENS * DIM  / 2];
__device__ uint32_t g_h1[(size_t)TOKENS * HMID / 2];
__device__ uint32_t g_h2[(size_t)TOKENS * HMID / 2];
__device__ uint32_t g_h3[(size_t)TOKENS * HLOW / 2];
__device__ uint32_t g_W1p[HMID * DIM  / 2];   // [M][K/2] transposed packed
__device__ uint32_t g_W2p[HMID * HMID / 2];
__device__ uint32_t g_W3p[HLOW * HMID / 2];
__device__ uint32_t g_W4p[DIM  * HLOW / 2];

// ---------------- small helpers ----------------
__device__ __forceinline__ uint32_t pack2(float a, float b) {
    __half2 h = __floats2half2_rn(a, b);
    return *(uint32_t*)&h;
}
__device__ __forceinline__ float gelu_exact(float v) {
    return 0.5f * v * (1.0f + erff(v * 0.70710678118654752440f));
}
__device__ __forceinline__ void cp_async16(uint32_t dst, const void* src) {
    asm volatile("cp.async.cg.shared.global [%0], [%1], 16;\n" :: "r"(dst), "l"(src));
}
// .noinc: arrival counts against the initialized expected count (producer threads).
__device__ __forceinline__ void cp_async_arrive_noinc(uint32_t mbar) {
    asm volatile("cp.async.mbarrier.arrive.noinc.shared::cta.b64 [%0];\n" :: "r"(mbar) : "memory");
}
__device__ __forceinline__ bool elect_one() {
    uint32_t p;
    asm volatile("{\n\t.reg .pred P;\n\telect.sync _|P, 0xFFFFFFFF;\n\tselp.b32 %0,1,0,P;\n\t}"
                 : "=r"(p));
    return p != 0;
}
#define MBAR_INIT(mbar, cnt) \
    asm volatile("mbarrier.init.shared.b64 [%0], %1;" :: "r"(mbar), "r"(cnt) : "memory")

__device__ __forceinline__ void mbar_wait(uint32_t mbar, uint32_t parity) {
    uint32_t done;
    asm volatile("{\n\t.reg .pred p;\n\t"
                 "mbarrier.try_wait.parity.acquire.cta.shared::cta.b64 p, [%1], %2;\n\t"
                 "selp.b32 %0, 1, 0, p;\n\t}"
                 : "=r"(done) : "r"(mbar), "r"(parity) : "memory");
    while (!done) {
        asm volatile("{\n\t.reg .pred p;\n\t"
                     "mbarrier.try_wait.parity.acquire.cta.shared::cta.b64 p, [%1], %2, 0x989680;\n\t"
                     "selp.b32 %0, 1, 0, p;\n\t}"
                     : "=r"(done) : "r"(mbar), "r"(parity) : "memory");
    }
}

#if TCGEN_OK
// ---------------- tcgen05 primitives (arch-specific target only) ----------------
#define TC_ALLOC(smem_addr, ncols) \
    asm volatile("tcgen05.alloc.cta_group::1.sync.aligned.shared::cta.b32 [%0], %1;" \
                 :: "r"(smem_addr), "r"(ncols) : "memory")
#define TC_RELINQ() \
    asm volatile("tcgen05.relinquish_alloc_permit.cta_group::1.sync.aligned;")
#define TC_DEALLOC(tmem, ncols) \
    asm volatile("tcgen05.dealloc.cta_group::1.sync.aligned.b32 %0, %1;" :: "r"(tmem), "r"(ncols))
#define TC_COMMIT(mbar) \
    asm volatile("tcgen05.commit.cta_group::1.mbarrier::arrive::one.shared::cluster.b64 [%0];" \
                 :: "r"(mbar) : "memory")
#define TC_FENCE_AFTER()  asm volatile("tcgen05.fence::after_thread_sync;" ::: "memory")
#define TC_FENCE_BEFORE() asm volatile("tcgen05.fence::before_thread_sync;" ::: "memory")
#define TC_WAIT_LD()      asm volatile("tcgen05.wait::ld.sync.aligned;" ::: "memory")

// SS-mode f16 MMA, cta_group::1, f32 accum
__device__ __forceinline__ void mma_f16_ss(uint32_t d, uint64_t adesc, uint64_t bdesc,
                                           uint32_t idesc, bool en) {
    uint32_t e = en ? 1u : 0u;
    asm volatile("{\n\t.reg .pred p;\n\tsetp.ne.u32 p, %5, 0;\n\t"
                 "tcgen05.mma.cta_group::1.kind::f16 [%0], %1, %2, %3, {%4,%4,%4,%4}, p;\n\t}"
                 :: "r"(d), "l"(adesc), "l"(bdesc), "r"(idesc), "r"(0u), "r"(e) : "memory");
}

#define LDTM32(r, addr) \
    asm volatile("tcgen05.ld.sync.aligned.32x32b.x32.b32 " \
        "{%0,%1,%2,%3,%4,%5,%6,%7,%8,%9,%10,%11,%12,%13,%14,%15," \
        "%16,%17,%18,%19,%20,%21,%22,%23,%24,%25,%26,%27,%28,%29,%30,%31}, [%32];" \
        : "=r"((r)[0]),  "=r"((r)[1]),  "=r"((r)[2]),  "=r"((r)[3]), \
          "=r"((r)[4]),  "=r"((r)[5]),  "=r"((r)[6]),  "=r"((r)[7]), \
          "=r"((r)[8]),  "=r"((r)[9]),  "=r"((r)[10]), "=r"((r)[11]), \
          "=r"((r)[12]), "=r"((r)[13]), "=r"((r)[14]), "=r"((r)[15]), \
          "=r"((r)[16]), "=r"((r)[17]), "=r"((r)[18]), "=r"((r)[19]), \
          "=r"((r)[20]), "=r"((r)[21]), "=r"((r)[22]), "=r"((r)[23]), \
          "=r"((r)[24]), "=r"((r)[25]), "=r"((r)[26]), "=r"((r)[27]), \
          "=r"((r)[28]), "=r"((r)[29]), "=r"((r)[30]), "=r"((r)[31]) \
        : "r"(addr))

// SW128 smem descriptor: layout=2, version=1, SBO=64, LBO=1
__device__ __forceinline__ uint64_t mk_desc(uint32_t addr) {
    const uint64_t base = (2ull << 61) | (1ull << 46) | (64ull << 32) | (1ull << 16);
    return base | ((uint64_t)(addr >> 4) & 0x3FFFull);
}
#endif  // TCGEN_OK

// ---------------- merged weight repack: W[K][M] fp32 -> Wt[M][K/2] fp16x2 ----------------
__device__ __forceinline__ void repack_one(const float* __restrict__ W, uint32_t* __restrict__ Wt,
                                           int M, int KU, int idx) {
    int kp = idx / M;
    int m  = idx - kp * M;
    float w0 = W[(size_t)(2 * kp)     * M + m];
    float w1 = W[(size_t)(2 * kp + 1) * M + m];
    Wt[(size_t)m * KU + kp] = pack2(w0, w1);
}
#define R1 (512 * 512)
#define R2 (R1 + 512 * 256)
#define R3 (R2 + 256 * 256)
#define R4 (R3 + 1024 * 128)
__global__ void convw_all_kernel(const float* __restrict__ W1, const float* __restrict__ W2,
                                 const float* __restrict__ W3, const float* __restrict__ W4) {
    int idx = blockIdx.x * blockDim.x + threadIdx.x;
    if (idx < R1)       repack_one(W1, g_W1p, HMID, DIM  / 2, idx);
    else if (idx < R2)  repack_one(W2, g_W2p, HMID, HMID / 2, idx - R1);
    else if (idx < R3)  repack_one(W3, g_W3p, HLOW, HMID / 2, idx - R2);
    else if (idx < R4)  repack_one(W4, g_W4p, DIM,  HLOW / 2, idx - R3);
}

// ---------------- LayerNorm: fp32 in -> fp16x2 out ----------------
__global__ void ln_kernel(const float* __restrict__ x, const float* __restrict__ gamma,
                          const float* __restrict__ beta) {
    int row = blockIdx.x;
    int tid = threadIdx.x;
    const float4* xr = (const float4*)(x + (size_t)row * DIM);
    float4 v = xr[tid];
    float s  = v.x + v.y + v.z + v.w;
    float sq = v.x * v.x + v.y * v.y + v.z * v.z + v.w * v.w;
    #pragma unroll
    for (int o = 16; o > 0; o >>= 1) {
        s  += __shfl_xor_sync(0xFFFFFFFFu, s,  o);
        sq += __shfl_xor_sync(0xFFFFFFFFu, sq, o);
    }
    __shared__ float ss[8], ssq[8];
    if ((tid & 31) == 0) { ss[tid >> 5] = s; ssq[tid >> 5] = sq; }
    __syncthreads();
    float S = 0.f, SQ = 0.f;
    #pragma unroll
    for (int i = 0; i < 8; i++) { S += ss[i]; SQ += ssq[i]; }
    float mu   = S * (1.0f / DIM);
    float var  = SQ * (1.0f / DIM) - mu * mu;
    float rstd = rsqrtf(var + 1e-5f);
    float4 gm = ((const float4*)gamma)[tid];
    float4 bt = ((const float4*)beta)[tid];
    uint2 o;
    o.x = pack2((v.x - mu) * rstd * gm.x + bt.x, (v.y - mu) * rstd * gm.y + bt.y);
    o.y = pack2((v.z - mu) * rstd * gm.z + bt.z, (v.w - mu) * rstd * gm.w + bt.w);
    ((uint2*)(g_h0 + (size_t)row * (DIM / 2)))[tid] = o;
}

// ---------------- tcgen05 fused GEMM, 128x256 tile, occupancy 2 ----------------
// CTA tile: 128 tokens x 256 outputs, K-tile 64. 2 smem stages x (A 16KB + B 32KB)
// = 96KB/CTA -> 2 CTAs/SM. TMEM: 256 cols/CTA (2 CTAs fill the 512-col pool).
// Warps 0-3 (128 thr): producers + epilogue. Warp 4: MMA (4 dispatches/K-tile).
// The point: with 2 CTAs/SM, one CTA's fma/alu epilogue overlaps the other
// CTA's tensor mainloop instead of serializing behind it.
#define STAGE_BYTES  49152
#define GEMM_SMEM_BYTES (2 * STAGE_BYTES + 1024 + 64)
#define NTHREADS 160

template<int K, int MOUT, int EPI>
__device__ __forceinline__ void gemm_tc_body(
    const uint32_t* __restrict__ A, const uint32_t* __restrict__ Wt,
    const float* __restrict__ bias, uint32_t* __restrict__ outp,
    const float* __restrict__ xres, float* __restrict__ fout)
{
#if TCGEN_OK
    constexpr int KU = K / 2;     // u32 per row
    constexpr int NT = K / 64;    // K-tiles
    extern __shared__ uint8_t smraw[];
    uint32_t base = ((uint32_t)__cvta_generic_to_shared(smraw) + 1023u) & ~1023u;
    const uint32_t tmemptr = base + 2u * STAGE_BYTES;
    const uint32_t fullB   = tmemptr + 16;    // full[0..1]:  +16,+24  (count 128)
    const uint32_t emptyB  = tmemptr + 32;    // empty[0..1]: +32,+40  (count 1)

    const int tid  = threadIdx.x;
    const int lane = tid & 31;
    const int warp = tid >> 5;
    const int bm = blockIdx.y;
    const int bn = blockIdx.x;

    if (tid == 0) {
        #pragma unroll
        for (int s = 0; s < 2; s++) {
            MBAR_INIT(fullB  + 8 * s, 128);
            MBAR_INIT(emptyB + 8 * s, 1);
        }
    }
    if (warp == 0) { TC_ALLOC(tmemptr, 256); TC_RELINQ(); }
    __syncthreads();
    uint32_t tmem;
    asm volatile("ld.shared.b32 %0, [%1];" : "=r"(tmem) : "r"(tmemptr));

    const uint32_t* gA = A  + (size_t)bm * 128 * KU;
    const uint32_t* gW = Wt + (size_t)bn * 256 * KU;

    if (warp < 4) {
        // ---------------- producers (128 threads, 24 chunks each per stage) ----------------
        for (int j = 0; j < NT; j++) {
            const int st = j & 1;
            if (j >= 2) mbar_wait(emptyB + 8 * st, (uint32_t)((j / 2 - 1) & 1));
            const int k0 = j * 32;
            const uint32_t stA = base + (uint32_t)st * STAGE_BYTES;
            const uint32_t stB = stA + 16384u;
            #pragma unroll
            for (int i = 0; i < 8; i++) {         // A: 128 rows x 8 chunks
                const int c  = i * 128 + tid;
                const int r  = c >> 3;
                const int ch = c & 7;
                const uint32_t sw = (uint32_t)(r * 128 + ((ch ^ (r & 7)) << 4));
                cp_async16(stA + sw, gA + (size_t)r * KU + k0 + ch * 4);
            }
            #pragma unroll
            for (int i = 0; i < 16; i++) {        // B: 256 rows x 8 chunks
                const int c  = i * 128 + tid;
                const int r  = c >> 3;
                const int ch = c & 7;
                const uint32_t sw = (uint32_t)(r * 128 + ((ch ^ (r & 7)) << 4));
                cp_async16(stB + sw, gW + (size_t)r * KU + k0 + ch * 4);
            }
            cp_async_arrive_noinc(fullB + 8 * st);
        }
    } else {
        // ---------------- MMA warp ----------------
        const uint32_t idesc = (1u << 4) | (32u << 17) | (8u << 24);  // f32 acc, f16, N=256, M=128
        for (int j = 0; j < NT; j++) {
            const int st = j & 1;
            mbar_wait(fullB + 8 * st, (uint32_t)((j / 2) & 1));
            TC_FENCE_AFTER();
            if (elect_one()) {
                const uint32_t stA = base + (uint32_t)st * STAGE_BYTES;
                uint64_t adesc = mk_desc(stA);
                uint64_t bdesc = mk_desc(stA + 16384u);
                bool enk = (j > 0);
                #pragma unroll
                for (int ks = 0; ks < 4; ks++)
                    mma_f16_ss(tmem, adesc + ks * 2, bdesc + ks * 2, idesc, enk || (ks > 0));
                TC_COMMIT(emptyB + 8 * st);
            }
        }
    }

    // all threads: wait for final MMA completion (producers have consumed all
    // earlier phases of this barrier sequentially, so no early-pass race)
    {
        const int last = NT - 1;
        mbar_wait(emptyB + 8 * (last & 1), (uint32_t)((last / 2) & 1));
    }
    TC_FENCE_AFTER();
    __syncthreads();

    // ---------------- epilogue: warps 0-3 read TMEM in 32-col chunks ----------------
    if (warp < 4) {
        const uint32_t tmw = tmem + ((uint32_t)warp << 21);
        const int row = bm * 128 + warp * 32 + lane;

        #pragma unroll
        for (int chunk = 0; chunk < 8; chunk++) {
            uint32_t r[32];
            LDTM32(r, tmw + (uint32_t)(chunk * 32));
            TC_WAIT_LD();
            const int c0 = bn * 256 + chunk * 32;
            if (EPI == 0) {
                uint32_t o[16];
                #pragma unroll
                for (int jj = 0; jj < 16; jj++) {
                    float2 bb = *(const float2*)&bias[c0 + 2 * jj];
                    o[jj] = pack2(gelu_exact(__uint_as_float(r[2 * jj])     + bb.x),
                                  gelu_exact(__uint_as_float(r[2 * jj + 1]) + bb.y));
                }
                uint4* dst = (uint4*)(outp + (size_t)row * (MOUT / 2) + (c0 >> 1));
                dst[0] = make_uint4(o[0],  o[1],  o[2],  o[3]);
                dst[1] = make_uint4(o[4],  o[5],  o[6],  o[7]);
                dst[2] = make_uint4(o[8],  o[9],  o[10], o[11]);
                dst[3] = make_uint4(o[12], o[13], o[14], o[15]);
            } else {
                #pragma unroll
                for (int q = 0; q < 8; q++) {
                    const float4 xv = *(const float4*)&xres[(size_t)row * MOUT + c0 + 4 * q];
                    float4 ov;
                    ov.x = xv.x + __uint_as_float(r[4 * q])     + bias[c0 + 4 * q];
                    ov.y = xv.y + __uint_as_float(r[4 * q + 1]) + bias[c0 + 4 * q + 1];
                    ov.z = xv.z + __uint_as_float(r[4 * q + 2]) + bias[c0 + 4 * q + 2];
                    ov.w = xv.w + __uint_as_float(r[4 * q + 3]) + bias[c0 + 4 * q + 3];
                    *(float4*)&fout[(size_t)row * MOUT + c0 + 4 * q] = ov;
                }
            }
        }
    }
    TC_FENCE_BEFORE();
    __syncthreads();
    if (warp == 0) TC_DEALLOC(tmem, 256);
#endif  // TCGEN_OK
}

__global__ void __launch_bounds__(NTHREADS, 2) gemm1_kernel(const float* __restrict__ bias) {
    gemm_tc_body<DIM, HMID, 0>(g_h0, g_W1p, bias, g_h1, nullptr, nullptr);
}
__global__ void __launch_bounds__(NTHREADS, 2) gemm2_kernel(const float* __restrict__ bias) {
    gemm_tc_body<HMID, HMID, 0>(g_h1, g_W2p, bias, g_h2, nullptr, nullptr);
}
__global__ void __launch_bounds__(NTHREADS, 2) gemm3_kernel(const float* __restrict__ bias) {
    gemm_tc_body<HMID, HLOW, 0>(g_h2, g_W3p, bias, g_h3, nullptr, nullptr);
}
__global__ void __launch_bounds__(NTHREADS, 2) gemm4_kernel(const float* __restrict__ bias,
                                                            const float* __restrict__ xres,
                                                            float* __restrict__ fout) {
    gemm_tc_body<HLOW, DIM, 1>(g_h3, g_W4p, bias, nullptr, xres, fout);
}

// ---------------- launch ----------------
extern "C" void kernel_launch(void* const* d_in, const int* in_sizes, int n_in,
                              void* d_out, int out_size) {
    const float* x     = (const float*)d_in[0];
    const float* gamma = (const float*)d_in[1];
    const float* beta  = (const float*)d_in[2];
    const float* W1    = (const float*)d_in[3];
    const float* b1    = (const float*)d_in[4];
    const float* W2    = (const float*)d_in[5];
    const float* b2    = (const float*)d_in[6];
    const float* W3    = (const float*)d_in[7];
    const float* b3    = (const float*)d_in[8];
    const float* W4    = (const float*)d_in[9];
    const float* b4    = (const float*)d_in[10];
    float* out = (float*)d_out;

    cudaFuncSetAttribute(gemm1_kernel, cudaFuncAttributeMaxDynamicSharedMemorySize, GEMM_SMEM_BYTES);
    cudaFuncSetAttribute(gemm2_kernel, cudaFuncAttributeMaxDynamicSharedMemorySize, GEMM_SMEM_BYTES);
    cudaFuncSetAttribute(gemm3_kernel, cudaFuncAttributeMaxDynamicSharedMemorySize, GEMM_SMEM_BYTES);
    cudaFuncSetAttribute(gemm4_kernel, cudaFuncAttributeMaxDynamicSharedMemorySize, GEMM_SMEM_BYTES);

    convw_all_kernel<<<(R4 + 255) / 256, 256>>>(W1, W2, W3, W4);
    ln_kernel<<<TOKENS, 256>>>(x, gamma, beta);

    gemm1_kernel<<<dim3(HMID / 256, TOKENS / 128), NTHREADS, GEMM_SMEM_BYTES>>>(b1);
    gemm2_kernel<<<dim3(HMID / 256, TOKENS / 128), NTHREADS, GEMM_SMEM_BYTES>>>(b2);
    gemm3_kernel<<<dim3(HLOW / 256, TOKENS / 128), NTHREADS, GEMM_SMEM_BYTES>>>(b3);
    gemm4_kernel<<<dim3(DIM  / 256, TOKENS / 128), NTHREADS, GEMM_SMEM_BYTES>>>(b4, x, out);
}

// round 16
// speedup vs baseline: 1.1294x; 1.1294x over previous
#include <cuda_runtime.h>
#include <cuda_fp16.h>
#include <cstdint>
#include <cstddef>

#define TOKENS 32768
#define DIM    1024
#define HMID   512
#define HLOW   256

#if defined(__CUDA_ARCH_FEAT_SM103_ALL) || defined(__CUDA_ARCH_FEAT_SM100_ALL) || \
    (defined(__CUDA_ARCH_SPECIFIC__) && (__CUDA_ARCH_SPECIFIC__ >= 1000))
#define TCGEN_OK 1
#else
#define TCGEN_OK 0
#endif

// ---------------- static device scratch (fp16x2 packed in u32) ----------------
__device__ uint32_t g_h0[(size_t)TOKENS * DIM  / 2];
__device__ uint32_t g_h1[(size_t)TOKENS * HMID / 2];
__device__ uint32_t g_h2[(size_t)TOKENS * HMID / 2];
__device__ uint32_t g_h3[(size_t)TOKENS * HLOW / 2];
__device__ uint32_t g_W1p[HMID * DIM  / 2];   // [M][K/2] transposed packed
__device__ uint32_t g_W2p[HMID * HMID / 2];
__device__ uint32_t g_W3p[HLOW * HMID / 2];
__device__ uint32_t g_W4p[DIM  * HLOW / 2];

// ---------------- small helpers ----------------
__device__ __forceinline__ uint32_t pack2(float a, float b) {
    __half2 h = __floats2half2_rn(a, b);
    return *(uint32_t*)&h;
}
__device__ __forceinline__ float gelu_exact(float v) {
    return 0.5f * v * (1.0f + erff(v * 0.70710678118654752440f));
}
__device__ __forceinline__ void cp_async16(uint32_t dst, const void* src) {
    asm volatile("cp.async.cg.shared.global [%0], [%1], 16;\n" :: "r"(dst), "l"(src));
}
// .noinc: arrival counts against the initialized expected count (producer threads).
__device__ __forceinline__ void cp_async_arrive_noinc(uint32_t mbar) {
    asm volatile("cp.async.mbarrier.arrive.noinc.shared::cta.b64 [%0];\n" :: "r"(mbar) : "memory");
}
__device__ __forceinline__ bool elect_one() {
    uint32_t p;
    asm volatile("{\n\t.reg .pred P;\n\telect.sync _|P, 0xFFFFFFFF;\n\tselp.b32 %0,1,0,P;\n\t}"
                 : "=r"(p));
    return p != 0;
}
#define MBAR_INIT(mbar, cnt) \
    asm volatile("mbarrier.init.shared.b64 [%0], %1;" :: "r"(mbar), "r"(cnt) : "memory")

__device__ __forceinline__ void mbar_wait(uint32_t mbar, uint32_t parity) {
    uint32_t done;
    asm volatile("{\n\t.reg .pred p;\n\t"
                 "mbarrier.try_wait.parity.acquire.cta.shared::cta.b64 p, [%1], %2;\n\t"
                 "selp.b32 %0, 1, 0, p;\n\t}"
                 : "=r"(done) : "r"(mbar), "r"(parity) : "memory");
    while (!done) {
        asm volatile("{\n\t.reg .pred p;\n\t"
                     "mbarrier.try_wait.parity.acquire.cta.shared::cta.b64 p, [%1], %2, 0x989680;\n\t"
                     "selp.b32 %0, 1, 0, p;\n\t}"
                     : "=r"(done) : "r"(mbar), "r"(parity) : "memory");
    }
}

#define STS128(a, r0, r1, r2, r3) \
    asm volatile("st.shared.v4.b32 [%0], {%1,%2,%3,%4};" \
                 :: "r"(a), "r"(r0), "r"(r1), "r"(r2), "r"(r3) : "memory")
#define LDS128(r0, r1, r2, r3, a) \
    asm volatile("ld.shared.v4.b32 {%0,%1,%2,%3}, [%4];" \
                 : "=r"(r0), "=r"(r1), "=r"(r2), "=r"(r3) : "r"(a))

#if TCGEN_OK
// ---------------- tcgen05 primitives (arch-specific target only) ----------------
#define TC_ALLOC(smem_addr, ncols) \
    asm volatile("tcgen05.alloc.cta_group::1.sync.aligned.shared::cta.b32 [%0], %1;" \
                 :: "r"(smem_addr), "r"(ncols) : "memory")
#define TC_RELINQ() \
    asm volatile("tcgen05.relinquish_alloc_permit.cta_group::1.sync.aligned;")
#define TC_DEALLOC(tmem, ncols) \
    asm volatile("tcgen05.dealloc.cta_group::1.sync.aligned.b32 %0, %1;" :: "r"(tmem), "r"(ncols))
#define TC_COMMIT(mbar) \
    asm volatile("tcgen05.commit.cta_group::1.mbarrier::arrive::one.shared::cluster.b64 [%0];" \
                 :: "r"(mbar) : "memory")
#define TC_FENCE_AFTER()  asm volatile("tcgen05.fence::after_thread_sync;" ::: "memory")
#define TC_FENCE_BEFORE() asm volatile("tcgen05.fence::before_thread_sync;" ::: "memory")
#define TC_WAIT_LD()      asm volatile("tcgen05.wait::ld.sync.aligned;" ::: "memory")

// SS-mode f16 MMA, cta_group::1, f32 accum
__device__ __forceinline__ void mma_f16_ss(uint32_t d, uint64_t adesc, uint64_t bdesc,
                                           uint32_t idesc, bool en) {
    uint32_t e = en ? 1u : 0u;
    asm volatile("{\n\t.reg .pred p;\n\tsetp.ne.u32 p, %5, 0;\n\t"
                 "tcgen05.mma.cta_group::1.kind::f16 [%0], %1, %2, %3, {%4,%4,%4,%4}, p;\n\t}"
                 :: "r"(d), "l"(adesc), "l"(bdesc), "r"(idesc), "r"(0u), "r"(e) : "memory");
}

#define LDTM32(r, addr) \
    asm volatile("tcgen05.ld.sync.aligned.32x32b.x32.b32 " \
        "{%0,%1,%2,%3,%4,%5,%6,%7,%8,%9,%10,%11,%12,%13,%14,%15," \
        "%16,%17,%18,%19,%20,%21,%22,%23,%24,%25,%26,%27,%28,%29,%30,%31}, [%32];" \
        : "=r"((r)[0]),  "=r"((r)[1]),  "=r"((r)[2]),  "=r"((r)[3]), \
          "=r"((r)[4]),  "=r"((r)[5]),  "=r"((r)[6]),  "=r"((r)[7]), \
          "=r"((r)[8]),  "=r"((r)[9]),  "=r"((r)[10]), "=r"((r)[11]), \
          "=r"((r)[12]), "=r"((r)[13]), "=r"((r)[14]), "=r"((r)[15]), \
          "=r"((r)[16]), "=r"((r)[17]), "=r"((r)[18]), "=r"((r)[19]), \
          "=r"((r)[20]), "=r"((r)[21]), "=r"((r)[22]), "=r"((r)[23]), \
          "=r"((r)[24]), "=r"((r)[25]), "=r"((r)[26]), "=r"((r)[27]), \
          "=r"((r)[28]), "=r"((r)[29]), "=r"((r)[30]), "=r"((r)[31]) \
        : "r"(addr))

// SW128 smem descriptor: layout=2, version=1, SBO=64, LBO=1
__device__ __forceinline__ uint64_t mk_desc(uint32_t addr) {
    const uint64_t base = (2ull << 61) | (1ull << 46) | (64ull << 32) | (1ull << 16);
    return base | ((uint64_t)(addr >> 4) & 0x3FFFull);
}
#endif  // TCGEN_OK

// ---------------- merged weight repack: W[K][M] fp32 -> Wt[M][K/2] fp16x2 ----------------
__device__ __forceinline__ void repack_one(const float* __restrict__ W, uint32_t* __restrict__ Wt,
                                           int M, int KU, int idx) {
    int kp = idx / M;
    int m  = idx - kp * M;
    float w0 = W[(size_t)(2 * kp)     * M + m];
    float w1 = W[(size_t)(2 * kp + 1) * M + m];
    Wt[(size_t)m * KU + kp] = pack2(w0, w1);
}
#define R1 (512 * 512)
#define R2 (R1 + 512 * 256)
#define R3 (R2 + 256 * 256)
#define R4 (R3 + 1024 * 128)
__global__ void convw_all_kernel(const float* __restrict__ W1, const float* __restrict__ W2,
                                 const float* __restrict__ W3, const float* __restrict__ W4) {
    int idx = blockIdx.x * blockDim.x + threadIdx.x;
    if (idx < R1)       repack_one(W1, g_W1p, HMID, DIM  / 2, idx);
    else if (idx < R2)  repack_one(W2, g_W2p, HMID, HMID / 2, idx - R1);
    else if (idx < R3)  repack_one(W3, g_W3p, HLOW, HMID / 2, idx - R2);
    else if (idx < R4)  repack_one(W4, g_W4p, DIM,  HLOW / 2, idx - R3);
}

// ---------------- LayerNorm: fp32 in -> fp16x2 out ----------------
__global__ void ln_kernel(const float* __restrict__ x, const float* __restrict__ gamma,
                          const float* __restrict__ beta) {
    int row = blockIdx.x;
    int tid = threadIdx.x;
    const float4* xr = (const float4*)(x + (size_t)row * DIM);
    float4 v = xr[tid];
    float s  = v.x + v.y + v.z + v.w;
    float sq = v.x * v.x + v.y * v.y + v.z * v.z + v.w * v.w;
    #pragma unroll
    for (int o = 16; o > 0; o >>= 1) {
        s  += __shfl_xor_sync(0xFFFFFFFFu, s,  o);
        sq += __shfl_xor_sync(0xFFFFFFFFu, sq, o);
    }
    __shared__ float ss[8], ssq[8];
    if ((tid & 31) == 0) { ss[tid >> 5] = s; ssq[tid >> 5] = sq; }
    __syncthreads();
    float S = 0.f, SQ = 0.f;
    #pragma unroll
    for (int i = 0; i < 8; i++) { S += ss[i]; SQ += ssq[i]; }
    float mu   = S * (1.0f / DIM);
    float var  = SQ * (1.0f / DIM) - mu * mu;
    float rstd = rsqrtf(var + 1e-5f);
    float4 gm = ((const float4*)gamma)[tid];
    float4 bt = ((const float4*)beta)[tid];
    uint2 o;
    o.x = pack2((v.x - mu) * rstd * gm.x + bt.x, (v.y - mu) * rstd * gm.y + bt.y);
    o.y = pack2((v.z - mu) * rstd * gm.z + bt.z, (v.w - mu) * rstd * gm.w + bt.w);
    ((uint2*)(g_h0 + (size_t)row * (DIM / 2)))[tid] = o;
}

// ---------------- tcgen05 fused GEMM, 128x256 tile, occupancy 2 ----------------
// CTA tile: 128 tokens x 256 outputs, K-tile 64. 2 smem stages x (A 16KB + B 32KB).
// NEW this round: the epilogue transposes through SMEM (reusing the now-idle
// stage-0 buffer, stride 144B = conflict-free) so all global stores — and
// gemm4's residual reads — are full-line coalesced (4 lines/instr instead of 32).
#define STAGE_BYTES  49152
#define GEMM_SMEM_BYTES (2 * STAGE_BYTES + 1024 + 64)
#define NTHREADS 160
#define EPI_STRIDE 144u

template<int K, int MOUT, int EPI>
__device__ __forceinline__ void gemm_tc_body(
    const uint32_t* __restrict__ A, const uint32_t* __restrict__ Wt,
    const float* __restrict__ bias, uint32_t* __restrict__ outp,
    const float* __restrict__ xres, float* __restrict__ fout)
{
#if TCGEN_OK
    constexpr int KU = K / 2;     // u32 per row
    constexpr int NT = K / 64;    // K-tiles
    extern __shared__ uint8_t smraw[];
    uint32_t base = ((uint32_t)__cvta_generic_to_shared(smraw) + 1023u) & ~1023u;
    const uint32_t tmemptr = base + 2u * STAGE_BYTES;
    const uint32_t fullB   = tmemptr + 16;    // full[0..1]:  +16,+24  (count 128)
    const uint32_t emptyB  = tmemptr + 32;    // empty[0..1]: +32,+40  (count 1)

    const int tid  = threadIdx.x;
    const int lane = tid & 31;
    const int warp = tid >> 5;
    const int bm = blockIdx.y;
    const int bn = blockIdx.x;

    if (tid == 0) {
        #pragma unroll
        for (int s = 0; s < 2; s++) {
            MBAR_INIT(fullB  + 8 * s, 128);
            MBAR_INIT(emptyB + 8 * s, 1);
        }
    }
    if (warp == 0) { TC_ALLOC(tmemptr, 256); TC_RELINQ(); }
    __syncthreads();
    uint32_t tmem;
    asm volatile("ld.shared.b32 %0, [%1];" : "=r"(tmem) : "r"(tmemptr));

    const uint32_t* gA = A  + (size_t)bm * 128 * KU;
    const uint32_t* gW = Wt + (size_t)bn * 256 * KU;

    if (warp < 4) {
        // ---------------- producers (128 threads, 24 chunks each per stage) ----------------
        for (int j = 0; j < NT; j++) {
            const int st = j & 1;
            if (j >= 2) mbar_wait(emptyB + 8 * st, (uint32_t)((j / 2 - 1) & 1));
            const int k0 = j * 32;
            const uint32_t stA = base + (uint32_t)st * STAGE_BYTES;
            const uint32_t stB = stA + 16384u;
            #pragma unroll
            for (int i = 0; i < 8; i++) {         // A: 128 rows x 8 chunks
                const int c  = i * 128 + tid;
                const int r  = c >> 3;
                const int ch = c & 7;
                const uint32_t sw = (uint32_t)(r * 128 + ((ch ^ (r & 7)) << 4));
                cp_async16(stA + sw, gA + (size_t)r * KU + k0 + ch * 4);
            }
            #pragma unroll
            for (int i = 0; i < 16; i++) {        // B: 256 rows x 8 chunks
                const int c  = i * 128 + tid;
                const int r  = c >> 3;
                const int ch = c & 7;
                const uint32_t sw = (uint32_t)(r * 128 + ((ch ^ (r & 7)) << 4));
                cp_async16(stB + sw, gW + (size_t)r * KU + k0 + ch * 4);
            }
            cp_async_arrive_noinc(fullB + 8 * st);
        }
    } else {
        // ---------------- MMA warp ----------------
        const uint32_t idesc = (1u << 4) | (32u << 17) | (8u << 24);  // f32 acc, f16, N=256, M=128
        for (int j = 0; j < NT; j++) {
            const int st = j & 1;
            mbar_wait(fullB + 8 * st, (uint32_t)((j / 2) & 1));
            TC_FENCE_AFTER();
            if (elect_one()) {
                const uint32_t stA = base + (uint32_t)st * STAGE_BYTES;
                uint64_t adesc = mk_desc(stA);
                uint64_t bdesc = mk_desc(stA + 16384u);
                bool enk = (j > 0);
                #pragma unroll
                for (int ks = 0; ks < 4; ks++)
                    mma_f16_ss(tmem, adesc + ks * 2, bdesc + ks * 2, idesc, enk || (ks > 0));
                TC_COMMIT(emptyB + 8 * st);
            }
        }
    }

    // all threads: wait for final MMA completion (producers have consumed all
    // earlier phases of this barrier sequentially, so no early-pass race)
    {
        const int last = NT - 1;
        mbar_wait(emptyB + 8 * (last & 1), (uint32_t)((last / 2) & 1));
    }
    TC_FENCE_AFTER();
    __syncthreads();   // stages now idle -> stage 0 becomes epilogue staging

    // ---------------- epilogue: transpose via SMEM, coalesced global I/O ----------------
    if (warp < 4) {
        const uint32_t tmw = tmem + ((uint32_t)warp << 21);
        const int rbase = warp * 32;                 // warp-private rows
        const uint32_t stg = base;                   // stage-0 reuse (18KB < 48KB)
        const uint32_t sa  = stg + (uint32_t)(rbase + lane) * EPI_STRIDE;

        if (EPI == 0) {
            #pragma unroll
            for (int p = 0; p < 4; p++) {            // 2 chunks (64 cols) per pass
                uint32_t r0[32], r1[32];
                LDTM32(r0, tmw + (uint32_t)(p * 64));
                LDTM32(r1, tmw + (uint32_t)(p * 64 + 32));
                TC_WAIT_LD();
                const int c0 = bn * 256 + p * 64;
                uint32_t o[32];
                #pragma unroll
                for (int jj = 0; jj < 16; jj++) {
                    float2 b0 = *(const float2*)&bias[c0 + 2 * jj];
                    float2 b1 = *(const float2*)&bias[c0 + 32 + 2 * jj];
                    o[jj]      = pack2(gelu_exact(__uint_as_float(r0[2 * jj])     + b0.x),
                                       gelu_exact(__uint_as_float(r0[2 * jj + 1]) + b0.y));
                    o[16 + jj] = pack2(gelu_exact(__uint_as_float(r1[2 * jj])     + b1.x),
                                       gelu_exact(__uint_as_float(r1[2 * jj + 1]) + b1.y));
                }
                #pragma unroll
                for (int q = 0; q < 8; q++)
                    STS128(sa + q * 16u, o[4 * q], o[4 * q + 1], o[4 * q + 2], o[4 * q + 3]);
                __syncwarp();
                #pragma unroll
                for (int i = 0; i < 8; i++) {        // coalesced: 4 rows x 128B per instr
                    const int rr = rbase + i * 4 + (lane >> 3);
                    const int q  = lane & 7;
                    uint32_t v0, v1, v2, v3;
                    LDS128(v0, v1, v2, v3, stg + (uint32_t)rr * EPI_STRIDE + (uint32_t)q * 16u);
                    *(uint4*)(outp + (size_t)(bm * 128 + rr) * (MOUT / 2) + (c0 >> 1) + q * 4) =
                        make_uint4(v0, v1, v2, v3);
                }
                __syncwarp();
            }
        } else {
            #pragma unroll
            for (int p = 0; p < 8; p++) {            // 1 chunk (32 fp32 cols) per pass
                uint32_t r0[32];
                LDTM32(r0, tmw + (uint32_t)(p * 32));
                TC_WAIT_LD();
                const int c0 = bn * 256 + p * 32;
                #pragma unroll
                for (int q = 0; q < 8; q++) {
                    const float4 bb = *(const float4*)&bias[c0 + 4 * q];
                    STS128(sa + q * 16u,
                           __float_as_uint(__uint_as_float(r0[4 * q])     + bb.x),
                           __float_as_uint(__uint_as_float(r0[4 * q + 1]) + bb.y),
                           __float_as_uint(__uint_as_float(r0[4 * q + 2]) + bb.z),
                           __float_as_uint(__uint_as_float(r0[4 * q + 3]) + bb.w));
                }
                __syncwarp();
                #pragma unroll
                for (int i = 0; i < 8; i++) {        // coalesced rd+wr: 4 rows x 128B
                    const int rr = rbase + i * 4 + (lane >> 3);
                    const int q  = lane & 7;
                    uint32_t v0, v1, v2, v3;
                    LDS128(v0, v1, v2, v3, stg + (uint32_t)rr * EPI_STRIDE + (uint32_t)q * 16u);
                    const float4 xv = *(const float4*)&xres[(size_t)(bm * 128 + rr) * MOUT + c0 + 4 * q];
                    float4 ov;
                    ov.x = xv.x + __uint_as_float(v0);
                    ov.y = xv.y + __uint_as_float(v1);
                    ov.z = xv.z + __uint_as_float(v2);
                    ov.w = xv.w + __uint_as_float(v3);
                    *(float4*)&fout[(size_t)(bm * 128 + rr) * MOUT + c0 + 4 * q] = ov;
                }
                __syncwarp();
            }
        }
    }
    TC_FENCE_BEFORE();
    __syncthreads();
    if (warp == 0) TC_DEALLOC(tmem, 256);
#endif  // TCGEN_OK
}

__global__ void __launch_bounds__(NTHREADS, 2) gemm1_kernel(const float* __restrict__ bias) {
    gemm_tc_body<DIM, HMID, 0>(g_h0, g_W1p, bias, g_h1, nullptr, nullptr);
}
__global__ void __launch_bounds__(NTHREADS, 2) gemm2_kernel(const float* __restrict__ bias) {
    gemm_tc_body<HMID, HMID, 0>(g_h1, g_W2p, bias, g_h2, nullptr, nullptr);
}
__global__ void __launch_bounds__(NTHREADS, 2) gemm3_kernel(const float* __restrict__ bias) {
    gemm_tc_body<HMID, HLOW, 0>(g_h2, g_W3p, bias, g_h3, nullptr, nullptr);
}
__global__ void __launch_bounds__(NTHREADS, 2) gemm4_kernel(const float* __restrict__ bias,
                                                            const float* __restrict__ xres,
                                                            float* __restrict__ fout) {
    gemm_tc_body<HLOW, DIM, 1>(g_h3, g_W4p, bias, nullptr, xres, fout);
}

// ---------------- launch ----------------
extern "C" void kernel_launch(void* const* d_in, const int* in_sizes, int n_in,
                              void* d_out, int out_size) {
    const float* x     = (const float*)d_in[0];
    const float* gamma = (const float*)d_in[1];
    const float* beta  = (const float*)d_in[2];
    const float* W1    = (const float*)d_in[3];
    const float* b1    = (const float*)d_in[4];
    const float* W2    = (const float*)d_in[5];
    const float* b2    = (const float*)d_in[6];
    const float* W3    = (const float*)d_in[7];
    const float* b3    = (const float*)d_in[8];
    const float* W4    = (const float*)d_in[9];
    const float* b4    = (const float*)d_in[10];
    float* out = (float*)d_out;

    cudaFuncSetAttribute(gemm1_kernel, cudaFuncAttributeMaxDynamicSharedMemorySize, GEMM_SMEM_BYTES);
    cudaFuncSetAttribute(gemm2_kernel, cudaFuncAttributeMaxDynamicSharedMemorySize, GEMM_SMEM_BYTES);
    cudaFuncSetAttribute(gemm3_kernel, cudaFuncAttributeMaxDynamicSharedMemorySize, GEMM_SMEM_BYTES);
    cudaFuncSetAttribute(gemm4_kernel, cudaFuncAttributeMaxDynamicSharedMemorySize, GEMM_SMEM_BYTES);

    convw_all_kernel<<<(R4 + 255) / 256, 256>>>(W1, W2, W3, W4);
    ln_kernel<<<TOKENS, 256>>>(x, gamma, beta);

    gemm1_kernel<<<dim3(HMID / 256, TOKENS / 128), NTHREADS, GEMM_SMEM_BYTES>>>(b1);
    gemm2_kernel<<<dim3(HMID / 256, TOKENS / 128), NTHREADS, GEMM_SMEM_BYTES>>>(b2);
    gemm3_kernel<<<dim3(HLOW / 256, TOKENS / 128), NTHREADS, GEMM_SMEM_BYTES>>>(b3);
    gemm4_kernel<<<dim3(DIM  / 256, TOKENS / 128), NTHREADS, GEMM_SMEM_BYTES>>>(b4, x, out);
}